// round 1
// baseline (speedup 1.0000x reference)
#include <cuda_runtime.h>
#include <cstdint>

// Problem constants
#define NB    32      // batch
#define LP    2048    // protein length
#define LDRG  256     // drug length (groups, gs=1)
#define DD    512     // model dim
#define GPNUM 512     // protein groups (2048/4)

// ---------------- scratch (static device memory; no allocation) ----------------
// layout (floats):
//   protg : 0         .. 8388608     [32,512,512]
//   QP    : 8388608                  [32,512,512]
//   KP    : 16777216
//   VP    : 25165824
//   QD    : 33554432                 [32,256,512]
//   KD    : 37748736
//   VD    : 41943040
//   S     : 46137344  (33554432)     [b,h,Lq,Lk] reused for both directions
__device__ float g_scratch[79691776];
__device__ unsigned char g_masks[24576];   // [0,16384) prot-group mask u8, [16384,24576) drug mask u8
__device__ int g_flag;                     // mask dtype: 0=u8, 1=i32, 2=f32

// ---------------- mask dtype detection + conversion ----------------
__device__ __forceinline__ bool read_mask(const void* p, int i, int f) {
  if (f == 0) return ((const unsigned char*)p)[i] != 0;
  if (f == 1) return ((const int*)p)[i] != 0;
  return ((const float*)p)[i] != 0.0f;
}

__global__ void detect_kernel(const unsigned char* __restrict__ p) {
  int big = 0, off = 0;
  for (int i = 0; i < 4096; ++i) {
    unsigned char c = p[i];
    big |= (c > 1) ? 1 : 0;
    off |= (c != 0 && (i & 3) != 0) ? 1 : 0;
  }
  // float32 1.0f bytes include 63/128 -> big. uint8 bool has ones at all offsets.
  // int32 0/1 has nonzero only at offsets %4==0.
  g_flag = big ? 2 : (off ? 0 : 1);
}

__global__ void mask_kernel(const void* __restrict__ mp, const void* __restrict__ md,
                            float* __restrict__ outMP, float* __restrict__ outMD) {
  int f = g_flag;
  int idx = blockIdx.x * blockDim.x + threadIdx.x;
  if (idx < NB * GPNUM) {
    int b = idx / GPNUM, g = idx % GPNUM;
    int base = b * LP + g * 4;
    bool any = false;
#pragma unroll
    for (int r = 0; r < 4; ++r) any = any || read_mask(mp, base + r, f);
    g_masks[idx] = any ? 1 : 0;
    outMP[idx] = any ? 1.0f : 0.0f;
  } else {
    int j = idx - NB * GPNUM;
    if (j < NB * LDRG) {
      bool v = read_mask(md, j, f);
      g_masks[16384 + j] = v ? 1 : 0;
      outMD[j] = v ? 1.0f : 0.0f;
    }
  }
}

// ---------------- protein grouping (mean over 4) ----------------
__global__ void group_kernel(const float* __restrict__ P, float* __restrict__ G) {
  int idx = blockIdx.x * 256 + threadIdx.x;   // exactly 32*512*512 threads
  int d = idx & 511;
  int g = (idx >> 9) & 511;
  int b = idx >> 18;
  const float* p = P + ((size_t)b * LP + (size_t)g * 4) * DD + d;
  G[idx] = 0.25f * (p[0] + p[512] + p[1024] + p[1536]);
}

// ---------------- GEMM tiles: BM=128, BN=64, BK=16, 128 threads, 8x8 micro ----
#define BM 128
#define BN 64
#define BK 16

// C[M,512] = A[M,512] * W[512,512]^T  (NT; y = x @ W.T)
__global__ __launch_bounds__(128) void gemm_proj(
    const float* __restrict__ A, const float* __restrict__ W, float* __restrict__ C) {
  __shared__ __align__(16) float As[BK][BM + 4];
  __shared__ __align__(16) float Bs[BK][BN + 4];
  const int tid = threadIdx.x;
  const int tx = tid & 7, ty = tid >> 3;
  const int mBase = blockIdx.x * BM;
  const int nBase = blockIdx.y * BN;
  float acc[8][8];
#pragma unroll
  for (int i = 0; i < 8; ++i)
#pragma unroll
    for (int j = 0; j < 8; ++j) acc[i][j] = 0.0f;

  for (int k0 = 0; k0 < 512; k0 += BK) {
#pragma unroll
    for (int i = tid * 4; i < BM * BK; i += 512) {
      int r = i >> 4, c = i & 15;
      float4 v = *(const float4*)(A + (size_t)(mBase + r) * 512 + k0 + c);
      As[c][r] = v.x; As[c + 1][r] = v.y; As[c + 2][r] = v.z; As[c + 3][r] = v.w;
    }
#pragma unroll
    for (int i = tid * 4; i < BN * BK; i += 512) {
      int r = i >> 4, c = i & 15;
      float4 v = *(const float4*)(W + (size_t)(nBase + r) * 512 + k0 + c);
      Bs[c][r] = v.x; Bs[c + 1][r] = v.y; Bs[c + 2][r] = v.z; Bs[c + 3][r] = v.w;
    }
    __syncthreads();
#pragma unroll
    for (int kk = 0; kk < BK; ++kk) {
      float4 a0 = *(const float4*)&As[kk][ty * 8];
      float4 a1 = *(const float4*)&As[kk][ty * 8 + 4];
      float4 b0 = *(const float4*)&Bs[kk][tx * 8];
      float4 b1 = *(const float4*)&Bs[kk][tx * 8 + 4];
      float a[8] = {a0.x, a0.y, a0.z, a0.w, a1.x, a1.y, a1.z, a1.w};
      float b[8] = {b0.x, b0.y, b0.z, b0.w, b1.x, b1.y, b1.z, b1.w};
#pragma unroll
      for (int i = 0; i < 8; ++i)
#pragma unroll
        for (int j = 0; j < 8; ++j) acc[i][j] += a[i] * b[j];
    }
    __syncthreads();
  }
#pragma unroll
  for (int i = 0; i < 8; ++i) {
    float* cp = C + (size_t)(mBase + ty * 8 + i) * 512 + nBase + tx * 8;
    *(float4*)cp = make_float4(acc[i][0], acc[i][1], acc[i][2], acc[i][3]);
    *(float4*)(cp + 4) = make_float4(acc[i][4], acc[i][5], acc[i][6], acc[i][7]);
  }
}

// S[b,h,l,k] = sum_d Q[b,l,h*64+d]*K[b,k,h*64+d], masked (-1e6 where !(mq&mk))
__global__ __launch_bounds__(128) void gemm_logits(
    const float* __restrict__ Q, const float* __restrict__ Km, float* __restrict__ S,
    const unsigned char* __restrict__ mq, const unsigned char* __restrict__ mk,
    int Lq, int Lk) {
  __shared__ __align__(16) float As[BK][BM + 4];
  __shared__ __align__(16) float Bs[BK][BN + 4];
  const int tid = threadIdx.x;
  const int tx = tid & 7, ty = tid >> 3;
  const int mBase = blockIdx.x * BM;
  const int nBase = blockIdx.y * BN;
  const int z = blockIdx.z;
  const int b = z >> 3, h = z & 7;
  const float* A = Q + (size_t)b * Lq * 512 + h * 64;
  const float* B = Km + (size_t)b * Lk * 512 + h * 64;
  float* C = S + (size_t)z * Lq * Lk;
  const unsigned char* mqb = mq + b * Lq;
  const unsigned char* mkb = mk + b * Lk;

  float acc[8][8];
#pragma unroll
  for (int i = 0; i < 8; ++i)
#pragma unroll
    for (int j = 0; j < 8; ++j) acc[i][j] = 0.0f;

  for (int k0 = 0; k0 < 64; k0 += BK) {
#pragma unroll
    for (int i = tid * 4; i < BM * BK; i += 512) {
      int r = i >> 4, c = i & 15;
      float4 v = *(const float4*)(A + (size_t)(mBase + r) * 512 + k0 + c);
      As[c][r] = v.x; As[c + 1][r] = v.y; As[c + 2][r] = v.z; As[c + 3][r] = v.w;
    }
#pragma unroll
    for (int i = tid * 4; i < BN * BK; i += 512) {
      int r = i >> 4, c = i & 15;
      float4 v = *(const float4*)(B + (size_t)(nBase + r) * 512 + k0 + c);
      Bs[c][r] = v.x; Bs[c + 1][r] = v.y; Bs[c + 2][r] = v.z; Bs[c + 3][r] = v.w;
    }
    __syncthreads();
#pragma unroll
    for (int kk = 0; kk < BK; ++kk) {
      float4 a0 = *(const float4*)&As[kk][ty * 8];
      float4 a1 = *(const float4*)&As[kk][ty * 8 + 4];
      float4 b0 = *(const float4*)&Bs[kk][tx * 8];
      float4 b1 = *(const float4*)&Bs[kk][tx * 8 + 4];
      float a[8] = {a0.x, a0.y, a0.z, a0.w, a1.x, a1.y, a1.z, a1.w};
      float bb[8] = {b0.x, b0.y, b0.z, b0.w, b1.x, b1.y, b1.z, b1.w};
#pragma unroll
      for (int i = 0; i < 8; ++i)
#pragma unroll
        for (int j = 0; j < 8; ++j) acc[i][j] += a[i] * bb[j];
    }
    __syncthreads();
  }
  unsigned char rm[8], cm[8];
#pragma unroll
  for (int i = 0; i < 8; ++i) rm[i] = mqb[mBase + ty * 8 + i];
#pragma unroll
  for (int j = 0; j < 8; ++j) cm[j] = mkb[nBase + tx * 8 + j];
#pragma unroll
  for (int i = 0; i < 8; ++i) {
    float vals[8];
#pragma unroll
    for (int j = 0; j < 8; ++j)
      vals[j] = acc[i][j] - ((rm[i] && cm[j]) ? 0.0f : 1.0e6f);
    float* cp = C + (size_t)(mBase + ty * 8 + i) * Lk + nBase + tx * 8;
    *(float4*)cp = make_float4(vals[0], vals[1], vals[2], vals[3]);
    *(float4*)(cp + 4) = make_float4(vals[4], vals[5], vals[6], vals[7]);
  }
}

// Out[b,l,h*64+n] = sum_k Alpha[b,h,l,k] * V[b,k,h*64+n]   (NN)
__global__ __launch_bounds__(128) void gemm_av(
    const float* __restrict__ Alp, const float* __restrict__ V, float* __restrict__ Out,
    int Lq, int Lk) {
  __shared__ __align__(16) float As[BK][BM + 4];
  __shared__ __align__(16) float Bs[BK][BN + 4];
  const int tid = threadIdx.x;
  const int tx = tid & 7, ty = tid >> 3;
  const int mBase = blockIdx.x * BM;
  const int z = blockIdx.z;
  const int b = z >> 3, h = z & 7;
  const float* A = Alp + (size_t)z * Lq * Lk;         // lda = Lk
  const float* B = V + (size_t)b * Lk * 512 + h * 64; // ldb = 512
  float* C = Out + (size_t)b * Lq * 512 + h * 64;     // ldc = 512

  float acc[8][8];
#pragma unroll
  for (int i = 0; i < 8; ++i)
#pragma unroll
    for (int j = 0; j < 8; ++j) acc[i][j] = 0.0f;

  for (int k0 = 0; k0 < Lk; k0 += BK) {
#pragma unroll
    for (int i = tid * 4; i < BM * BK; i += 512) {
      int r = i >> 4, c = i & 15;
      float4 v = *(const float4*)(A + (size_t)(mBase + r) * Lk + k0 + c);
      As[c][r] = v.x; As[c + 1][r] = v.y; As[c + 2][r] = v.z; As[c + 3][r] = v.w;
    }
#pragma unroll
    for (int i = tid * 4; i < BK * BN; i += 512) {
      int r = i >> 6, c = i & 63;
      float4 v = *(const float4*)(B + (size_t)(k0 + r) * 512 + c);
      *(float4*)&Bs[r][c] = v;
    }
    __syncthreads();
#pragma unroll
    for (int kk = 0; kk < BK; ++kk) {
      float4 a0 = *(const float4*)&As[kk][ty * 8];
      float4 a1 = *(const float4*)&As[kk][ty * 8 + 4];
      float4 b0 = *(const float4*)&Bs[kk][tx * 8];
      float4 b1 = *(const float4*)&Bs[kk][tx * 8 + 4];
      float a[8] = {a0.x, a0.y, a0.z, a0.w, a1.x, a1.y, a1.z, a1.w};
      float bb[8] = {b0.x, b0.y, b0.z, b0.w, b1.x, b1.y, b1.z, b1.w};
#pragma unroll
      for (int i = 0; i < 8; ++i)
#pragma unroll
        for (int j = 0; j < 8; ++j) acc[i][j] += a[i] * bb[j];
    }
    __syncthreads();
  }
#pragma unroll
  for (int i = 0; i < 8; ++i) {
    float* cp = C + (size_t)(mBase + ty * 8 + i) * 512 + tx * 8;
    *(float4*)cp = make_float4(acc[i][0], acc[i][1], acc[i][2], acc[i][3]);
    *(float4*)(cp + 4) = make_float4(acc[i][4], acc[i][5], acc[i][6], acc[i][7]);
  }
}

// ---------------- softmax: block per (b,l), warp per head ----------------
// Reads S[b,h,l,:], writes normalized alpha back into S (for AV GEMM) and to the
// output buffer in [b,l,k,h] layout with fully-coalesced stores.
template <int LK>
__global__ __launch_bounds__(256) void softmax_kernel(
    float* __restrict__ S, const unsigned char* __restrict__ mq,
    float* __restrict__ alphaOut, int Lq) {
  __shared__ float sb[8][LK + 1];
  const int l = blockIdx.x, b = blockIdx.y;
  const int tid = threadIdx.x, w = tid >> 5, lane = tid & 31;
  const size_t abase = ((size_t)b * Lq + l) * (size_t)(LK * 8);

  if (!mq[b * Lq + l]) {
    for (int idx = tid; idx < LK * 8; idx += 256) alphaOut[abase + idx] = 0.0f;
#pragma unroll
    for (int h = 0; h < 8; ++h) {
      float* srow = S + ((size_t)(b * 8 + h) * Lq + l) * LK;
      for (int k = tid; k < LK; k += 256) srow[k] = 0.0f;
    }
    return;
  }

  float* srow = S + ((size_t)(b * 8 + w) * Lq + l) * LK;
  const int nit = LK / 32;
  float v[LK / 32];
  float mx = -3.0e38f;
#pragma unroll
  for (int i = 0; i < nit; ++i) { v[i] = srow[lane + 32 * i]; mx = fmaxf(mx, v[i]); }
#pragma unroll
  for (int o = 16; o > 0; o >>= 1) mx = fmaxf(mx, __shfl_xor_sync(0xffffffffu, mx, o));
  float sum = 0.0f;
#pragma unroll
  for (int i = 0; i < nit; ++i) { float e = expf(v[i] - mx); v[i] = e; sum += e; }
#pragma unroll
  for (int o = 16; o > 0; o >>= 1) sum += __shfl_xor_sync(0xffffffffu, sum, o);
  float inv = 1.0f / sum;
#pragma unroll
  for (int i = 0; i < nit; ++i) {
    float a = v[i] * inv;
    srow[lane + 32 * i] = a;
    sb[w][lane + 32 * i] = a;
  }
  __syncthreads();
#pragma unroll 4
  for (int idx = tid; idx < LK * 8; idx += 256) {
    int k = idx >> 3, h = idx & 7;
    alphaOut[abase + idx] = sb[h][k];
  }
}

// ---------------- launch ----------------
extern "C" void kernel_launch(void* const* d_in, const int* in_sizes, int n_in,
                              void* d_out, int out_size) {
  const float* protein = (const float*)d_in[0];
  const float* drug    = (const float*)d_in[1];
  const void*  mpraw   = d_in[2];
  const void*  mdraw   = d_in[3];
  const float* Wqp = (const float*)d_in[4];
  const float* Wkp = (const float*)d_in[5];
  const float* Wvp = (const float*)d_in[6];
  const float* Wqd = (const float*)d_in[7];
  const float* Wkd = (const float*)d_in[8];
  const float* Wvd = (const float*)d_in[9];
  float* out = (float*)d_out;

  float* sc = nullptr;
  cudaGetSymbolAddress((void**)&sc, g_scratch);
  unsigned char* mg = nullptr;
  cudaGetSymbolAddress((void**)&mg, g_masks);

  float* protg = sc;
  float* QP = sc + 8388608;
  float* KP = sc + 16777216;
  float* VP = sc + 25165824;
  float* QD = sc + 33554432;
  float* KD = sc + 37748736;
  float* VD = sc + 41943040;
  float* Sb = sc + 46137344;
  unsigned char* mpg = mg;
  unsigned char* mdg = mg + 16384;

  // output layout (float32, concatenated in reference return order)
  const size_t OFF_PROT = 0;          // [32,512,512]
  const size_t OFF_DRUG = 8388608;    // [32,256,512]
  const size_t OFF_MP   = 12582912;   // [32,512]
  const size_t OFF_MD   = 12599296;   // [32,256]
  const size_t OFF_APD  = 12607488;   // [32,512,256,8]
  const size_t OFF_ADP  = 46161920;   // [32,256,512,8]

  detect_kernel<<<1, 1>>>((const unsigned char*)mpraw);
  mask_kernel<<<96, 256>>>(mpraw, mdraw, out + OFF_MP, out + OFF_MD);
  group_kernel<<<32768, 256>>>(protein, protg);

  // projections: y = x @ W.T
  gemm_proj<<<dim3(128, 8), 128>>>(protg, Wqp, QP);
  gemm_proj<<<dim3(128, 8), 128>>>(protg, Wkp, KP);
  gemm_proj<<<dim3(128, 8), 128>>>(protg, Wvp, VP);
  gemm_proj<<<dim3(64, 8), 128>>>(drug, Wqd, QD);
  gemm_proj<<<dim3(64, 8), 128>>>(drug, Wkd, KD);
  gemm_proj<<<dim3(64, 8), 128>>>(drug, Wvd, VD);

  // protein->drug attention: Lq=512 (prot groups), Lk=256 (drug)
  gemm_logits<<<dim3(4, 4, 256), 128>>>(QP, KD, Sb, mpg, mdg, 512, 256);
  softmax_kernel<256><<<dim3(512, 32), 256>>>(Sb, mpg, out + OFF_APD, 512);
  gemm_av<<<dim3(4, 1, 256), 128>>>(Sb, VD, out + OFF_PROT, 512, 256);

  // drug->protein attention: Lq=256, Lk=512
  gemm_logits<<<dim3(2, 8, 256), 128>>>(QD, KP, Sb, mdg, mpg, 256, 512);
  softmax_kernel<512><<<dim3(256, 32), 256>>>(Sb, mdg, out + OFF_ADP, 256);
  gemm_av<<<dim3(2, 1, 256), 128>>>(Sb, VP, out + OFF_DRUG, 256, 512);

  (void)in_sizes; (void)n_in; (void)out_size;
}